// round 15
// baseline (speedup 1.0000x reference)
#include <cuda_runtime.h>
#include <cstdint>
#include <cstddef>

// Problem constants
#define NB 4
#define NS 2048
#define NH 16
#define NDK 64
#define NDM 1024
#define NT (NB * NS)          // 8192 tokens
#define ATTN_SCALE 0.125f     // 1/sqrt(64)

// ---------------------------------------------------------------------------
// Scratch (device globals: no cudaMalloc allowed)
// g_q/g_k/g_v hold TF32-PREROUNDED values (cvt.rna at qkv epilogue;
// idempotent -> flash consuming them raw is bit-identical).
// ---------------------------------------------------------------------------
__device__ float g_q[(size_t)NB * NH * NS * NDK];        // 33.5 MB  [b][h][s][d]
__device__ float g_k[(size_t)NB * NH * NS * NDK];        // 33.5 MB
__device__ float g_v[(size_t)NB * NH * NS * NDK];        // 33.5 MB
__device__ float g_ctx[(size_t)NT * NDM];                // 33.5 MB  [b][s][h*64+d]

// ---------------------------------------------------------------------------
// Helpers
// ---------------------------------------------------------------------------
__device__ __forceinline__ unsigned f2tf_u(float f) {
    unsigned u;
    asm("cvt.rna.tf32.f32 %0, %1;" : "=r"(u) : "f"(f));
    return u;
}

__device__ __forceinline__ float f2tf(float f) {
    return __uint_as_float(f2tf_u(f));
}

__device__ __forceinline__ void mma_m16n8k8(float* c, const unsigned* a, const unsigned* b) {
    asm volatile(
        "mma.sync.aligned.m16n8k8.row.col.f32.tf32.tf32.f32 "
        "{%0,%1,%2,%3},{%4,%5,%6,%7},{%8,%9},{%0,%1,%2,%3};\n"
        : "+f"(c[0]), "+f"(c[1]), "+f"(c[2]), "+f"(c[3])
        : "r"(a[0]), "r"(a[1]), "r"(a[2]), "r"(a[3]), "r"(b[0]), "r"(b[1]));
}

__device__ __forceinline__ void cp_a16(float* smem_dst, const float* gsrc) {
    unsigned s = (unsigned)__cvta_generic_to_shared(smem_dst);
    asm volatile("cp.async.cg.shared.global [%0], [%1], 16;\n" :: "r"(s), "l"(gsrc));
}

// ---------------------------------------------------------------------------
// Double-buffered GEMM body (round-7/12 measured config: 351us, tensor=49%).
// ---------------------------------------------------------------------------
#define GEMM_SMEM_FLOATS (2 * 128 * 36 * 2)
#define GEMM_SMEM_BYTES  (GEMM_SMEM_FLOATS * 4)

__device__ __forceinline__ void gemm_tn_128x128_db(
    const float* __restrict__ A, const float* __restrict__ Bw, int Kd,
    float* sm, float acc[4][4][4])
{
    float* As = sm;                      // [2][128][36]
    float* Bs = sm + 2 * 128 * 36;       // [2][128][36]
    const int tid  = threadIdx.x;
    const int lane = tid & 31, warp = tid >> 5;
    const int g = lane >> 2, t = lane & 3;
    const int wm0 = (warp & 1) * 64, wn0 = (warp >> 1) * 32;

    const int nIter = Kd / 32;

    #pragma unroll
    for (int i = 0; i < 4; i++) {
        int s = tid + i * 256;
        int r = s >> 3, c4 = (s & 7) << 2;
        cp_a16(&As[(size_t)r * 36 + c4], A  + (size_t)r * Kd + c4);
        cp_a16(&Bs[(size_t)r * 36 + c4], Bw + (size_t)r * Kd + c4);
    }
    asm volatile("cp.async.commit_group;\n");

    for (int it = 0; it < nIter; it++) {
        const int cur = it & 1;
        if (it + 1 < nIter) {
            const int nxt = cur ^ 1;
            const int k0  = (it + 1) * 32;
            #pragma unroll
            for (int i = 0; i < 4; i++) {
                int s = tid + i * 256;
                int r = s >> 3, c4 = (s & 7) << 2;
                cp_a16(&As[((size_t)nxt * 128 + r) * 36 + c4], A  + (size_t)r * Kd + k0 + c4);
                cp_a16(&Bs[((size_t)nxt * 128 + r) * 36 + c4], Bw + (size_t)r * Kd + k0 + c4);
            }
            asm volatile("cp.async.commit_group;\n");
            asm volatile("cp.async.wait_group 1;\n");
        } else {
            asm volatile("cp.async.wait_group 0;\n");
        }
        __syncthreads();

        const float* Asb = As + (size_t)cur * 128 * 36;
        const float* Bsb = Bs + (size_t)cur * 128 * 36;

        #pragma unroll
        for (int ks = 0; ks < 32; ks += 8) {
            unsigned a[4][4], b[4][2];
            #pragma unroll
            for (int mi = 0; mi < 4; mi++) {
                int m = wm0 + mi * 16 + g;
                a[mi][0] = f2tf_u(Asb[(size_t)(m    ) * 36 + ks + t    ]);
                a[mi][1] = f2tf_u(Asb[(size_t)(m + 8) * 36 + ks + t    ]);
                a[mi][2] = f2tf_u(Asb[(size_t)(m    ) * 36 + ks + t + 4]);
                a[mi][3] = f2tf_u(Asb[(size_t)(m + 8) * 36 + ks + t + 4]);
            }
            #pragma unroll
            for (int ni = 0; ni < 4; ni++) {
                int n = wn0 + ni * 8 + g;
                b[ni][0] = f2tf_u(Bsb[(size_t)n * 36 + ks + t    ]);
                b[ni][1] = f2tf_u(Bsb[(size_t)n * 36 + ks + t + 4]);
            }
            #pragma unroll
            for (int mi = 0; mi < 4; mi++)
                #pragma unroll
                for (int ni = 0; ni < 4; ni++)
                    mma_m16n8k8(acc[mi][ni], a[mi], b[ni]);
        }
        __syncthreads();
    }
}

// ---------------------------------------------------------------------------
// Kernel 1: fused QKV projection, TF32-prerounded epilogue (measured 351us).
// ---------------------------------------------------------------------------
__global__ __launch_bounds__(256) void qkv_proj_kernel(
    const float* __restrict__ Qin, const float* __restrict__ Kin, const float* __restrict__ Vin,
    const float* __restrict__ Wq,  const float* __restrict__ Wk,  const float* __restrict__ Wv,
    const float* __restrict__ bq,  const float* __restrict__ bk,  const float* __restrict__ bv)
{
    extern __shared__ float smg[];
    const int z = blockIdx.z;
    const float* X    = (z == 0) ? Qin : (z == 1) ? Kin : Vin;
    const float* W    = (z == 0) ? Wq  : (z == 1) ? Wk  : Wv;
    const float* bias = (z == 0) ? bq  : (z == 1) ? bk  : bv;
    float* out        = (z == 0) ? g_q : (z == 1) ? g_k : g_v;

    float acc[4][4][4];
    #pragma unroll
    for (int i = 0; i < 4; i++)
        #pragma unroll
        for (int j = 0; j < 4; j++)
            #pragma unroll
            for (int k = 0; k < 4; k++) acc[i][j][k] = 0.f;

    gemm_tn_128x128_db(X + (size_t)blockIdx.y * 128 * NDM,
                       W + (size_t)blockIdx.x * 128 * NDM, NDM, smg, acc);

    const int tid = threadIdx.x, lane = tid & 31, warp = tid >> 5;
    const int g = lane >> 2, t = lane & 3;
    const int wm0 = (warp & 1) * 64, wn0 = (warp >> 1) * 32;
    const int row0 = blockIdx.y * 128, col0 = blockIdx.x * 128;

    #pragma unroll
    for (int mi = 0; mi < 4; mi++) {
        #pragma unroll
        for (int ni = 0; ni < 4; ni++) {
            int n = col0 + wn0 + ni * 8 + 2 * t;
            int h = n >> 6, d = n & 63;
            float b0v = bias[n], b1v = bias[n + 1];
            #pragma unroll
            for (int half = 0; half < 2; half++) {
                int m  = row0 + wm0 + mi * 16 + g + half * 8;
                int bb = m >> 11, s = m & 2047;
                size_t idx = (((size_t)(bb * NH + h) * NS) + s) * NDK + d;
                *(float2*)(out + idx) = make_float2(f2tf(acc[mi][ni][half * 2 + 0] + b0v),
                                                    f2tf(acc[mi][ni][half * 2 + 1] + b1v));
            }
        }
    }
}

// ---------------------------------------------------------------------------
// Kernel 2: flash attention, SPLIT-KEY 16 warps (512 thr, 4 warps/SMSP).
// Warp pair (w, w+8) shares q-rows [16w,16w+16); w handles keys 0-63 of each
// k-tile, w+8 keys 64-127. Cross-warp online-softmax combine via pmax/psum
// SMEM; both warps compute identical al/rs so partial O accumulators add at
// the epilogue (upper warps park theirs in the dead Qs region).
// Permuted-K sigma trick retained (P stays in registers). TF32-prerounded
// q/k/v -> no cvt on fragment loads.
// SMEM: Qs[128][68] + Ks[2][128][68] + Vs[128][72] + pmax/psum[2][128] each
//     = 143360 B -> 1 CTA/SM.
// ---------------------------------------------------------------------------
#define QS_STRIDE 68
#define KS_STRIDE 68
#define VS_STRIDE 72
#define OB_STRIDE 66
#define ATTN_SMEM_FLOATS (128 * (QS_STRIDE + 2 * KS_STRIDE + VS_STRIDE) + 512)
#define ATTN_SMEM_BYTES  (ATTN_SMEM_FLOATS * 4)

__global__ __launch_bounds__(512, 1) void flash_attn_kernel(const float* __restrict__ relpos)
{
    extern __shared__ float sm[];
    float* Qs   = sm;                                 // [128][68]; obuf[128][66] in epilogue
    float* Ks   = Qs + 128 * QS_STRIDE;               // [2][128][68] (rows sigma-permuted)
    float* Vs   = Ks + 2 * 128 * KS_STRIDE;           // [128][72]   (rows natural)
    float* pmax = Vs + 128 * VS_STRIDE;               // [2][128]
    float* psum = pmax + 256;                         // [2][128]

    const int b = blockIdx.x, qt = blockIdx.y, h = blockIdx.z;
    const int bh = b * NH + h;
    const float* qp = g_q + (size_t)bh * NS * NDK + (size_t)qt * 128 * NDK;
    const float* kp = g_k + (size_t)bh * NS * NDK;
    const float* vp = g_v + (size_t)bh * NS * NDK;
    const float* rp = relpos + (size_t)h * NS * NS + (size_t)qt * 128 * NS;

    const int tid = threadIdx.x, lane = tid & 31, warp = tid >> 5;
    const int g = lane >> 2, t = lane & 3;
    const int side = warp >> 3;            // 0: keys 0-63, 1: keys 64-127
    const int wq   = warp & 7;
    const int wm   = wq * 16;              // q-row base for this warp
    const int kofs = side * 64;            // key offset within tile

    // prologue: Q (natural) + K(0) (sigma rows) in one group. 2048 chunks/tile.
    #pragma unroll
    for (int i = 0; i < 4; i++) {
        int s = tid + i * 512;
        int r = s >> 4, c4 = (s & 15) << 2;
        cp_a16(&Qs[(size_t)r * QS_STRIDE + c4], qp + (size_t)r * NDK + c4);
        int c = r & 7;
        int srow = (r & ~7) | ((c >> 1) + ((c & 1) << 2));   // sigma
        cp_a16(&Ks[(size_t)r * KS_STRIDE + c4], kp + (size_t)srow * NDK + c4);
    }
    asm volatile("cp.async.commit_group;\n");

    float rm0 = -INFINITY, rm1 = -INFINITY;
    float rs0 = 0.f, rs1 = 0.f;
    float oacc[8][4];
    #pragma unroll
    for (int i = 0; i < 8; i++)
        #pragma unroll
        for (int j = 0; j < 4; j++) oacc[i][j] = 0.f;

    for (int kt = 0; kt < NS / 128; kt++) {
        const int cur = kt & 1;

        // ---- group GV(kt): V(kt) natural ----
        {
            const float* vsrc = vp + (size_t)kt * 128 * NDK;
            #pragma unroll
            for (int i = 0; i < 4; i++) {
                int s = tid + i * 512;
                int r = s >> 4, c4 = (s & 15) << 2;
                cp_a16(&Vs[(size_t)r * VS_STRIDE + c4], vsrc + (size_t)r * NDK + c4);
            }
            asm volatile("cp.async.commit_group;\n");
        }
        // ---- group GK(kt): K(kt+1) sigma rows ----
        if (kt + 1 < NS / 128) {
            const float* ksrc = kp + (size_t)(kt + 1) * 128 * NDK;
            float* kdst = Ks + (size_t)(cur ^ 1) * 128 * KS_STRIDE;
            #pragma unroll
            for (int i = 0; i < 4; i++) {
                int s = tid + i * 512;
                int r = s >> 4, c4 = (s & 15) << 2;
                int c = r & 7;
                int srow = (r & ~7) | ((c >> 1) + ((c & 1) << 2));
                cp_a16(&kdst[(size_t)r * KS_STRIDE + c4], ksrc + (size_t)srow * NDK + c4);
            }
            asm volatile("cp.async.commit_group;\n");
            asm volatile("cp.async.wait_group 2;\n");   // drain K(kt) [and Q]
        } else {
            asm volatile("cp.async.wait_group 1;\n");   // drain K(kt)
        }
        __syncthreads();                                 // bar 1

        const float* Ksb = Ks + (size_t)cur * 128 * KS_STRIDE;

        // ---- S = Q K^T over this warp's 64 keys (8 key-blocks) ----
        float sacc[8][4];
        #pragma unroll
        for (int i = 0; i < 8; i++)
            #pragma unroll
            for (int j = 0; j < 4; j++) sacc[i][j] = 0.f;

        #pragma unroll
        for (int ks = 0; ks < 8; ks++) {
            unsigned qa[4];
            qa[0] = __float_as_uint(Qs[(size_t)(wm + g    ) * QS_STRIDE + ks * 8 + t    ]);
            qa[1] = __float_as_uint(Qs[(size_t)(wm + g + 8) * QS_STRIDE + ks * 8 + t    ]);
            qa[2] = __float_as_uint(Qs[(size_t)(wm + g    ) * QS_STRIDE + ks * 8 + t + 4]);
            qa[3] = __float_as_uint(Qs[(size_t)(wm + g + 8) * QS_STRIDE + ks * 8 + t + 4]);
            #pragma unroll
            for (int ni = 0; ni < 8; ni++) {
                unsigned bb[2];
                int n = kofs + ni * 8 + g;
                bb[0] = __float_as_uint(Ksb[(size_t)n * KS_STRIDE + ks * 8 + t    ]);
                bb[1] = __float_as_uint(Ksb[(size_t)n * KS_STRIDE + ks * 8 + t + 4]);
                mma_m16n8k8(sacc[ni], qa, bb);
            }
        }

        // ---- scale + relpos (per-KEY cols), partial row-max ----
        float m0 = -INFINITY, m1 = -INFINITY;
        const float* rp0 = rp + (size_t)(wm + g    ) * NS + kt * 128 + kofs + t;
        const float* rp1 = rp + (size_t)(wm + g + 8) * NS + kt * 128 + kofs + t;
        #pragma unroll
        for (int ni = 0; ni < 8; ni++) {
            sacc[ni][0] = sacc[ni][0] * ATTN_SCALE + rp0[ni * 8    ];
            sacc[ni][1] = sacc[ni][1] * ATTN_SCALE + rp0[ni * 8 + 4];
            sacc[ni][2] = sacc[ni][2] * ATTN_SCALE + rp1[ni * 8    ];
            sacc[ni][3] = sacc[ni][3] * ATTN_SCALE + rp1[ni * 8 + 4];
            m0 = fmaxf(m0, fmaxf(sacc[ni][0], sacc[ni][1]));
            m1 = fmaxf(m1, fmaxf(sacc[ni][2], sacc[ni][3]));
        }
        m0 = fmaxf(m0, __shfl_xor_sync(0xFFFFFFFFu, m0, 1));
        m0 = fmaxf(m0, __shfl_xor_sync(0xFFFFFFFFu, m0, 2));
        m1 = fmaxf(m1, __shfl_xor_sync(0xFFFFFFFFu, m1, 1));
        m1 = fmaxf(m1, __shfl_xor_sync(0xFFFFFFFFu, m1, 2));
        if (t == 0) {
            pmax[side * 128 + wm + g    ] = m0;
            pmax[side * 128 + wm + g + 8] = m1;
        }
        __syncthreads();                                 // bar 2: pmax published

        float nm0 = fmaxf(rm0, fmaxf(pmax[wm + g    ], pmax[128 + wm + g    ]));
        float nm1 = fmaxf(rm1, fmaxf(pmax[wm + g + 8], pmax[128 + wm + g + 8]));
        float al0 = __expf(rm0 - nm0), al1 = __expf(rm1 - nm1);
        rm0 = nm0; rm1 = nm1;

        // ---- P = exp(S - m), partial row sums ----
        float ps0 = 0.f, ps1 = 0.f;
        #pragma unroll
        for (int ni = 0; ni < 8; ni++) {
            sacc[ni][0] = __expf(sacc[ni][0] - nm0);
            sacc[ni][1] = __expf(sacc[ni][1] - nm0);
            sacc[ni][2] = __expf(sacc[ni][2] - nm1);
            sacc[ni][3] = __expf(sacc[ni][3] - nm1);
            ps0 += sacc[ni][0] + sacc[ni][1];
            ps1 += sacc[ni][2] + sacc[ni][3];
        }
        ps0 += __shfl_xor_sync(0xFFFFFFFFu, ps0, 1);
        ps0 += __shfl_xor_sync(0xFFFFFFFFu, ps0, 2);
        ps1 += __shfl_xor_sync(0xFFFFFFFFu, ps1, 1);
        ps1 += __shfl_xor_sync(0xFFFFFFFFu, ps1, 2);
        if (t == 0) {
            psum[side * 128 + wm + g    ] = ps0;
            psum[side * 128 + wm + g + 8] = ps1;
        }

        // ---- V(kt) visibility + psum publish in one barrier ----
        if (kt + 1 < NS / 128) {
            asm volatile("cp.async.wait_group 1;\n");
        } else {
            asm volatile("cp.async.wait_group 0;\n");
        }
        __syncthreads();                                 // bar 3

        rs0 = rs0 * al0 + psum[wm + g    ] + psum[128 + wm + g    ];
        rs1 = rs1 * al1 + psum[wm + g + 8] + psum[128 + wm + g + 8];

        #pragma unroll
        for (int nj = 0; nj < 8; nj++) {
            oacc[nj][0] *= al0; oacc[nj][1] *= al0;
            oacc[nj][2] *= al1; oacc[nj][3] *= al1;
        }

        // ---- O += P V over this warp's 64 keys ----
        #pragma unroll
        for (int ni = 0; ni < 8; ni++) {
            unsigned aP[4];
            aP[0] = f2tf_u(sacc[ni][0]);
            aP[1] = f2tf_u(sacc[ni][2]);
            aP[2] = f2tf_u(sacc[ni][1]);
            aP[3] = f2tf_u(sacc[ni][3]);
            int vr = kofs + ni * 8 + t;
            #pragma unroll
            for (int nj = 0; nj < 8; nj++) {
                unsigned bb[2];
                int n = nj * 8 + g;
                bb[0] = __float_as_uint(Vs[(size_t)(vr    ) * VS_STRIDE + n]);
                bb[1] = __float_as_uint(Vs[(size_t)(vr + 4) * VS_STRIDE + n]);
                mma_m16n8k8(oacc[nj], aP, bb);
            }
        }
        __syncthreads();                                 // bar 4: Vs/Ks reuse
    }

    // ---- epilogue: cross-warp O combine, normalize, write ctx ----
    float inv0 = 1.f / rs0, inv1 = 1.f / rs1;
    float* obuf = sm;   // reuse Qs region: [128][66]
    if (side == 1) {
        #pragma unroll
        for (int nj = 0; nj < 8; nj++) {
            int col = nj * 8 + 2 * t;
            *(float2*)&obuf[(size_t)(wm + g    ) * OB_STRIDE + col] =
                make_float2(oacc[nj][0], oacc[nj][1]);
            *(float2*)&obuf[(size_t)(wm + g + 8) * OB_STRIDE + col] =
                make_float2(oacc[nj][2], oacc[nj][3]);
        }
    }
    __syncthreads();
    if (side == 0) {
        #pragma unroll
        for (int nj = 0; nj < 8; nj++) {
            int col = nj * 8 + 2 * t;
            float2 u0 = *(float2*)&obuf[(size_t)(wm + g    ) * OB_STRIDE + col];
            float2 u1 = *(float2*)&obuf[(size_t)(wm + g + 8) * OB_STRIDE + col];
            size_t i0 = ((size_t)b * NS + qt * 128 + wm + g    ) * NDM + h * 64 + col;
            size_t i1 = ((size_t)b * NS + qt * 128 + wm + g + 8) * NDM + h * 64 + col;
            *(float2*)(g_ctx + i0) = make_float2((oacc[nj][0] + u0.x) * inv0,
                                                 (oacc[nj][1] + u0.y) * inv0);
            *(float2*)(g_ctx + i1) = make_float2((oacc[nj][2] + u1.x) * inv1,
                                                 (oacc[nj][3] + u1.y) * inv1);
        }
    }
}

// ---------------------------------------------------------------------------
// Kernel 3: out = ctx @ Wo^T + bo (measured configuration).
// ---------------------------------------------------------------------------
__global__ __launch_bounds__(256) void out_proj_kernel(
    const float* __restrict__ Wo, const float* __restrict__ bo, float* __restrict__ out)
{
    extern __shared__ float smg[];
    float acc[4][4][4];
    #pragma unroll
    for (int i = 0; i < 4; i++)
        #pragma unroll
        for (int j = 0; j < 4; j++)
            #pragma unroll
            for (int k = 0; k < 4; k++) acc[i][j][k] = 0.f;

    gemm_tn_128x128_db(g_ctx + (size_t)blockIdx.y * 128 * NDM,
                       Wo    + (size_t)blockIdx.x * 128 * NDM, NDM, smg, acc);

    const int tid = threadIdx.x, lane = tid & 31, warp = tid >> 5;
    const int g = lane >> 2, t = lane & 3;
    const int wm0 = (warp & 1) * 64, wn0 = (warp >> 1) * 32;
    const int row0 = blockIdx.y * 128, col0 = blockIdx.x * 128;

    #pragma unroll
    for (int mi = 0; mi < 4; mi++) {
        #pragma unroll
        for (int ni = 0; ni < 4; ni++) {
            int n = col0 + wn0 + ni * 8 + 2 * t;
            float b0v = bo[n], b1v = bo[n + 1];
            #pragma unroll
            for (int half = 0; half < 2; half++) {
                int m = row0 + wm0 + mi * 16 + g + half * 8;
                *(float2*)(out + (size_t)m * NDM + n) =
                    make_float2(acc[mi][ni][half * 2 + 0] + b0v,
                                acc[mi][ni][half * 2 + 1] + b1v);
            }
        }
    }
}

// ---------------------------------------------------------------------------
// Launch
// ---------------------------------------------------------------------------
extern "C" void kernel_launch(void* const* d_in, const int* in_sizes, int n_in,
                              void* d_out, int out_size)
{
    (void)in_sizes; (void)n_in; (void)out_size;
    const float* Q      = (const float*)d_in[0];
    const float* K      = (const float*)d_in[1];
    const float* V      = (const float*)d_in[2];
    const float* Wq     = (const float*)d_in[3];
    const float* bq     = (const float*)d_in[4];
    const float* Wk     = (const float*)d_in[5];
    const float* bk     = (const float*)d_in[6];
    const float* Wv     = (const float*)d_in[7];
    const float* bv     = (const float*)d_in[8];
    const float* Wo     = (const float*)d_in[9];
    const float* bo     = (const float*)d_in[10];
    const float* relpos = (const float*)d_in[11];
    float* out = (float*)d_out;

    cudaFuncSetAttribute(flash_attn_kernel,
                         cudaFuncAttributeMaxDynamicSharedMemorySize, ATTN_SMEM_BYTES);
    cudaFuncSetAttribute(qkv_proj_kernel,
                         cudaFuncAttributeMaxDynamicSharedMemorySize, GEMM_SMEM_BYTES);
    cudaFuncSetAttribute(out_proj_kernel,
                         cudaFuncAttributeMaxDynamicSharedMemorySize, GEMM_SMEM_BYTES);

    // 1) q,k,v = proj(Q/K/V), head-split, TF32-prerounded
    qkv_proj_kernel<<<dim3(NDM / 128, NT / 128, 3), dim3(256), GEMM_SMEM_BYTES>>>(
        Q, K, V, Wq, Wk, Wv, bq, bk, bv);
    // 2) fused attention, split-key 16 warps
    flash_attn_kernel<<<dim3(NB, NS / 128, NH), dim3(512), ATTN_SMEM_BYTES>>>(relpos);
    // 3) out = ctx @ Wo^T + bo
    out_proj_kernel<<<dim3(NDM / 128, NT / 128, 1), dim3(256), GEMM_SMEM_BYTES>>>(Wo, bo, out);
}

// round 16
// speedup vs baseline: 1.0539x; 1.0539x over previous
#include <cuda_runtime.h>
#include <cstdint>
#include <cstddef>

// Problem constants
#define NB 4
#define NS 2048
#define NH 16
#define NDK 64
#define NDM 1024
#define NT (NB * NS)          // 8192 tokens
#define ATTN_SCALE 0.125f     // 1/sqrt(64) = 2^-3 (exact power of two)

// ---------------------------------------------------------------------------
// Scratch (device globals: no cudaMalloc allowed)
// g_q/g_k/g_v hold TF32-PREROUNDED values (cvt.rna at qkv epilogue;
// idempotent -> flash consuming them raw is bit-identical).
// ---------------------------------------------------------------------------
__device__ float g_q[(size_t)NB * NH * NS * NDK];        // 33.5 MB  [b][h][s][d]
__device__ float g_k[(size_t)NB * NH * NS * NDK];        // 33.5 MB
__device__ float g_v[(size_t)NB * NH * NS * NDK];        // 33.5 MB
__device__ float g_ctx[(size_t)NT * NDM];                // 33.5 MB  [b][s][h*64+d]

// ---------------------------------------------------------------------------
// Helpers
// ---------------------------------------------------------------------------
__device__ __forceinline__ unsigned f2tf_u(float f) {
    unsigned u;
    asm("cvt.rna.tf32.f32 %0, %1;" : "=r"(u) : "f"(f));
    return u;
}

__device__ __forceinline__ float f2tf(float f) {
    return __uint_as_float(f2tf_u(f));
}

__device__ __forceinline__ void mma_m16n8k8(float* c, const unsigned* a, const unsigned* b) {
    asm volatile(
        "mma.sync.aligned.m16n8k8.row.col.f32.tf32.tf32.f32 "
        "{%0,%1,%2,%3},{%4,%5,%6,%7},{%8,%9},{%0,%1,%2,%3};\n"
        : "+f"(c[0]), "+f"(c[1]), "+f"(c[2]), "+f"(c[3])
        : "r"(a[0]), "r"(a[1]), "r"(a[2]), "r"(a[3]), "r"(b[0]), "r"(b[1]));
}

__device__ __forceinline__ void cp_a16(float* smem_dst, const float* gsrc) {
    unsigned s = (unsigned)__cvta_generic_to_shared(smem_dst);
    asm volatile("cp.async.cg.shared.global [%0], [%1], 16;\n" :: "r"(s), "l"(gsrc));
}

// ---------------------------------------------------------------------------
// Double-buffered GEMM body (measured config: 351us, tensor=49%).
// ---------------------------------------------------------------------------
#define GEMM_SMEM_FLOATS (2 * 128 * 36 * 2)
#define GEMM_SMEM_BYTES  (GEMM_SMEM_FLOATS * 4)

__device__ __forceinline__ void gemm_tn_128x128_db(
    const float* __restrict__ A, const float* __restrict__ Bw, int Kd,
    float* sm, float acc[4][4][4])
{
    float* As = sm;                      // [2][128][36]
    float* Bs = sm + 2 * 128 * 36;       // [2][128][36]
    const int tid  = threadIdx.x;
    const int lane = tid & 31, warp = tid >> 5;
    const int g = lane >> 2, t = lane & 3;
    const int wm0 = (warp & 1) * 64, wn0 = (warp >> 1) * 32;

    const int nIter = Kd / 32;

    #pragma unroll
    for (int i = 0; i < 4; i++) {
        int s = tid + i * 256;
        int r = s >> 3, c4 = (s & 7) << 2;
        cp_a16(&As[(size_t)r * 36 + c4], A  + (size_t)r * Kd + c4);
        cp_a16(&Bs[(size_t)r * 36 + c4], Bw + (size_t)r * Kd + c4);
    }
    asm volatile("cp.async.commit_group;\n");

    for (int it = 0; it < nIter; it++) {
        const int cur = it & 1;
        if (it + 1 < nIter) {
            const int nxt = cur ^ 1;
            const int k0  = (it + 1) * 32;
            #pragma unroll
            for (int i = 0; i < 4; i++) {
                int s = tid + i * 256;
                int r = s >> 3, c4 = (s & 7) << 2;
                cp_a16(&As[((size_t)nxt * 128 + r) * 36 + c4], A  + (size_t)r * Kd + k0 + c4);
                cp_a16(&Bs[((size_t)nxt * 128 + r) * 36 + c4], Bw + (size_t)r * Kd + k0 + c4);
            }
            asm volatile("cp.async.commit_group;\n");
            asm volatile("cp.async.wait_group 1;\n");
        } else {
            asm volatile("cp.async.wait_group 0;\n");
        }
        __syncthreads();

        const float* Asb = As + (size_t)cur * 128 * 36;
        const float* Bsb = Bs + (size_t)cur * 128 * 36;

        #pragma unroll
        for (int ks = 0; ks < 32; ks += 8) {
            unsigned a[4][4], b[4][2];
            #pragma unroll
            for (int mi = 0; mi < 4; mi++) {
                int m = wm0 + mi * 16 + g;
                a[mi][0] = f2tf_u(Asb[(size_t)(m    ) * 36 + ks + t    ]);
                a[mi][1] = f2tf_u(Asb[(size_t)(m + 8) * 36 + ks + t    ]);
                a[mi][2] = f2tf_u(Asb[(size_t)(m    ) * 36 + ks + t + 4]);
                a[mi][3] = f2tf_u(Asb[(size_t)(m + 8) * 36 + ks + t + 4]);
            }
            #pragma unroll
            for (int ni = 0; ni < 4; ni++) {
                int n = wn0 + ni * 8 + g;
                b[ni][0] = f2tf_u(Bsb[(size_t)n * 36 + ks + t    ]);
                b[ni][1] = f2tf_u(Bsb[(size_t)n * 36 + ks + t + 4]);
            }
            #pragma unroll
            for (int mi = 0; mi < 4; mi++)
                #pragma unroll
                for (int ni = 0; ni < 4; ni++)
                    mma_m16n8k8(acc[mi][ni], a[mi], b[ni]);
        }
        __syncthreads();
    }
}

// ---------------------------------------------------------------------------
// Kernel 1: fused QKV projection, TF32-prerounded epilogue (measured 351us).
// ---------------------------------------------------------------------------
__global__ __launch_bounds__(256) void qkv_proj_kernel(
    const float* __restrict__ Qin, const float* __restrict__ Kin, const float* __restrict__ Vin,
    const float* __restrict__ Wq,  const float* __restrict__ Wk,  const float* __restrict__ Wv,
    const float* __restrict__ bq,  const float* __restrict__ bk,  const float* __restrict__ bv)
{
    extern __shared__ float smg[];
    const int z = blockIdx.z;
    const float* X    = (z == 0) ? Qin : (z == 1) ? Kin : Vin;
    const float* W    = (z == 0) ? Wq  : (z == 1) ? Wk  : Wv;
    const float* bias = (z == 0) ? bq  : (z == 1) ? bk  : bv;
    float* out        = (z == 0) ? g_q : (z == 1) ? g_k : g_v;

    float acc[4][4][4];
    #pragma unroll
    for (int i = 0; i < 4; i++)
        #pragma unroll
        for (int j = 0; j < 4; j++)
            #pragma unroll
            for (int k = 0; k < 4; k++) acc[i][j][k] = 0.f;

    gemm_tn_128x128_db(X + (size_t)blockIdx.y * 128 * NDM,
                       W + (size_t)blockIdx.x * 128 * NDM, NDM, smg, acc);

    const int tid = threadIdx.x, lane = tid & 31, warp = tid >> 5;
    const int g = lane >> 2, t = lane & 3;
    const int wm0 = (warp & 1) * 64, wn0 = (warp >> 1) * 32;
    const int row0 = blockIdx.y * 128, col0 = blockIdx.x * 128;

    #pragma unroll
    for (int mi = 0; mi < 4; mi++) {
        #pragma unroll
        for (int ni = 0; ni < 4; ni++) {
            int n = col0 + wn0 + ni * 8 + 2 * t;
            int h = n >> 6, d = n & 63;
            float b0v = bias[n], b1v = bias[n + 1];
            #pragma unroll
            for (int half = 0; half < 2; half++) {
                int m  = row0 + wm0 + mi * 16 + g + half * 8;
                int bb = m >> 11, s = m & 2047;
                size_t idx = (((size_t)(bb * NH + h) * NS) + s) * NDK + d;
                *(float2*)(out + idx) = make_float2(f2tf(acc[mi][ni][half * 2 + 0] + b0v),
                                                    f2tf(acc[mi][ni][half * 2 + 1] + b1v));
            }
        }
    }
}

// ---------------------------------------------------------------------------
// Kernel 2: flash attention — round-12 structure (best measured) + relpos
// latency hidden by ACCUMULATOR SEEDING:
//   (QK^T)*s + rp == ((QK^T) + rp*8)*s  exactly, since s = 2^-3 (both
//   multiplies are pure exponent shifts). rp*8 is loaded into sacc at the
//   TOP of the iteration (before the K-wait), so the LDG latency is hidden
//   behind the barrier wait + the 128-MMA S chain instead of being exposed
//   between S-MMA and softmax.
// 8 warps / 256 threads (split-key 16-warp variant measured WORSE; reverted).
// Permuted-K sigma trick (P in registers); TF32-prerounded q/k/v.
// ---------------------------------------------------------------------------
#define QS_STRIDE 68
#define KS_STRIDE 68
#define VS_STRIDE 72
#define ATTN_SMEM_FLOATS (128 * (QS_STRIDE + 2 * KS_STRIDE + VS_STRIDE))
#define ATTN_SMEM_BYTES  (ATTN_SMEM_FLOATS * 4)

__global__ __launch_bounds__(256, 1) void flash_attn_kernel(const float* __restrict__ relpos)
{
    extern __shared__ float sm[];
    float* Qs = sm;                                   // [128][68]
    float* Ks = Qs + 128 * QS_STRIDE;                 // [2][128][68] (rows sigma-permuted)
    float* Vs = Ks + 2 * 128 * KS_STRIDE;             // [128][72]   (rows natural)

    const int b = blockIdx.x, qt = blockIdx.y, h = blockIdx.z;
    const int bh = b * NH + h;
    const float* qp = g_q + (size_t)bh * NS * NDK + (size_t)qt * 128 * NDK;
    const float* kp = g_k + (size_t)bh * NS * NDK;
    const float* vp = g_v + (size_t)bh * NS * NDK;
    const float* rp = relpos + (size_t)h * NS * NS + (size_t)qt * 128 * NS;

    const int tid = threadIdx.x, lane = tid & 31, warp = tid >> 5;
    const int g = lane >> 2, t = lane & 3;
    const int wm = warp * 16;

    // prologue: Q (natural) + K(0) (sigma rows) in one cp.async group.
    #pragma unroll
    for (int i = 0; i < 8; i++) {
        int s = tid + i * 256;
        int r = s >> 4, c4 = (s & 15) << 2;
        cp_a16(&Qs[(size_t)r * QS_STRIDE + c4], qp + (size_t)r * NDK + c4);
        int c = r & 7;
        int srow = (r & ~7) | ((c >> 1) + ((c & 1) << 2));   // sigma
        cp_a16(&Ks[(size_t)r * KS_STRIDE + c4], kp + (size_t)srow * NDK + c4);
    }
    asm volatile("cp.async.commit_group;\n");

    float rm0 = -INFINITY, rm1 = -INFINITY;   // running max, rows (wm+g), (wm+g+8)
    float rs0 = 0.f, rs1 = 0.f;               // running sum
    float oacc[8][4];
    #pragma unroll
    for (int i = 0; i < 8; i++)
        #pragma unroll
        for (int j = 0; j < 4; j++) oacc[i][j] = 0.f;

    unsigned qreg[8][4];                      // Q fragments, loaded at kt==0

    for (int kt = 0; kt < NS / 128; kt++) {
        const int cur = kt & 1;

        // ---- seed S accumulators with relpos*8 (exact; hides relpos LDG
        //      latency behind K-wait + S-MMA chain) ----
        float sacc[16][4];
        {
            const float* rp0 = rp + (size_t)(wm + g    ) * NS + kt * 128 + t;
            const float* rp1 = rp + (size_t)(wm + g + 8) * NS + kt * 128 + t;
            #pragma unroll
            for (int ni = 0; ni < 16; ni++) {
                sacc[ni][0] = rp0[ni * 8    ] * 8.f;
                sacc[ni][1] = rp0[ni * 8 + 4] * 8.f;
                sacc[ni][2] = rp1[ni * 8    ] * 8.f;
                sacc[ni][3] = rp1[ni * 8 + 4] * 8.f;
            }
        }

        // ---- group GV(kt): V(kt) -> Vs (natural rows) ----
        {
            const float* vsrc = vp + (size_t)kt * 128 * NDK;
            #pragma unroll
            for (int i = 0; i < 8; i++) {
                int s = tid + i * 256;
                int r = s >> 4, c4 = (s & 15) << 2;
                cp_a16(&Vs[(size_t)r * VS_STRIDE + c4], vsrc + (size_t)r * NDK + c4);
            }
            asm volatile("cp.async.commit_group;\n");
        }
        // ---- group GK(kt): K(kt+1) -> Ks[nxt] (sigma rows) ----
        if (kt + 1 < NS / 128) {
            const float* ksrc = kp + (size_t)(kt + 1) * 128 * NDK;
            float* kdst = Ks + (size_t)(cur ^ 1) * 128 * KS_STRIDE;
            #pragma unroll
            for (int i = 0; i < 8; i++) {
                int s = tid + i * 256;
                int r = s >> 4, c4 = (s & 15) << 2;
                int c = r & 7;
                int srow = (r & ~7) | ((c >> 1) + ((c & 1) << 2));
                cp_a16(&kdst[(size_t)r * KS_STRIDE + c4], ksrc + (size_t)srow * NDK + c4);
            }
            asm volatile("cp.async.commit_group;\n");
            asm volatile("cp.async.wait_group 2;\n");   // drain K(kt) [and Q]
        } else {
            asm volatile("cp.async.wait_group 1;\n");   // drain K(kt)
        }
        __syncthreads();

        if (kt == 0) {
            // Q is prerounded: plain bitcast loads, no cvt.
            #pragma unroll
            for (int ks = 0; ks < 8; ks++) {
                qreg[ks][0] = __float_as_uint(Qs[(size_t)(wm + g    ) * QS_STRIDE + ks * 8 + t    ]);
                qreg[ks][1] = __float_as_uint(Qs[(size_t)(wm + g + 8) * QS_STRIDE + ks * 8 + t    ]);
                qreg[ks][2] = __float_as_uint(Qs[(size_t)(wm + g    ) * QS_STRIDE + ks * 8 + t + 4]);
                qreg[ks][3] = __float_as_uint(Qs[(size_t)(wm + g + 8) * QS_STRIDE + ks * 8 + t + 4]);
            }
        }

        const float* Ksb = Ks + (size_t)cur * 128 * KS_STRIDE;

        // ---- S = rp*8 + Q K^T : warp tile m16 x n128(slots), k=64 ----
        #pragma unroll
        for (int ks = 0; ks < 8; ks++) {
            #pragma unroll
            for (int ni = 0; ni < 16; ni++) {
                unsigned bb[2];
                int n = ni * 8 + g;
                bb[0] = __float_as_uint(Ksb[(size_t)n * KS_STRIDE + ks * 8 + t    ]);
                bb[1] = __float_as_uint(Ksb[(size_t)n * KS_STRIDE + ks * 8 + t + 4]);
                mma_m16n8k8(sacc[ni], qreg[ks], bb);
            }
        }

        // ---- scale by 2^-3 (exact), tile row-max ----
        float m0 = -INFINITY, m1 = -INFINITY;
        #pragma unroll
        for (int ni = 0; ni < 16; ni++) {
            sacc[ni][0] *= ATTN_SCALE;
            sacc[ni][1] *= ATTN_SCALE;
            sacc[ni][2] *= ATTN_SCALE;
            sacc[ni][3] *= ATTN_SCALE;
            m0 = fmaxf(m0, fmaxf(sacc[ni][0], sacc[ni][1]));
            m1 = fmaxf(m1, fmaxf(sacc[ni][2], sacc[ni][3]));
        }
        m0 = fmaxf(m0, __shfl_xor_sync(0xFFFFFFFFu, m0, 1));
        m0 = fmaxf(m0, __shfl_xor_sync(0xFFFFFFFFu, m0, 2));
        m1 = fmaxf(m1, __shfl_xor_sync(0xFFFFFFFFu, m1, 1));
        m1 = fmaxf(m1, __shfl_xor_sync(0xFFFFFFFFu, m1, 2));

        float nm0 = fmaxf(rm0, m0), nm1 = fmaxf(rm1, m1);
        float al0 = __expf(rm0 - nm0), al1 = __expf(rm1 - nm1);
        rm0 = nm0; rm1 = nm1;

        // ---- P = exp(S - m) in registers, row sums ----
        float ps0 = 0.f, ps1 = 0.f;
        #pragma unroll
        for (int ni = 0; ni < 16; ni++) {
            sacc[ni][0] = __expf(sacc[ni][0] - nm0);
            sacc[ni][1] = __expf(sacc[ni][1] - nm0);
            sacc[ni][2] = __expf(sacc[ni][2] - nm1);
            sacc[ni][3] = __expf(sacc[ni][3] - nm1);
            ps0 += sacc[ni][0] + sacc[ni][1];
            ps1 += sacc[ni][2] + sacc[ni][3];
        }
        ps0 += __shfl_xor_sync(0xFFFFFFFFu, ps0, 1);
        ps0 += __shfl_xor_sync(0xFFFFFFFFu, ps0, 2);
        ps1 += __shfl_xor_sync(0xFFFFFFFFu, ps1, 1);
        ps1 += __shfl_xor_sync(0xFFFFFFFFu, ps1, 2);
        rs0 = rs0 * al0 + ps0;
        rs1 = rs1 * al1 + ps1;

        // rescale O accumulator
        #pragma unroll
        for (int ni = 0; ni < 8; ni++) {
            oacc[ni][0] *= al0; oacc[ni][1] *= al0;
            oacc[ni][2] *= al1; oacc[ni][3] *= al1;
        }

        // ---- V(kt) visible; K(kt+1) may continue in flight ----
        if (kt + 1 < NS / 128) {
            asm volatile("cp.async.wait_group 1;\n");
        } else {
            asm volatile("cp.async.wait_group 0;\n");
        }
        __syncthreads();

        // ---- O += P V : P A-fragments straight from sacc (permuted match) ----
        #pragma unroll
        for (int ni = 0; ni < 16; ni++) {          // key-block = k-block
            unsigned aP[4];
            aP[0] = f2tf_u(sacc[ni][0]);   // (row g,   k=t)
            aP[1] = f2tf_u(sacc[ni][2]);   // (row g+8, k=t)
            aP[2] = f2tf_u(sacc[ni][1]);   // (row g,   k=t+4)
            aP[3] = f2tf_u(sacc[ni][3]);   // (row g+8, k=t+4)
            #pragma unroll
            for (int nj = 0; nj < 8; nj++) {
                unsigned bb[2];
                int n = nj * 8 + g;
                bb[0] = __float_as_uint(Vs[(size_t)(ni * 8 + t    ) * VS_STRIDE + n]);
                bb[1] = __float_as_uint(Vs[(size_t)(ni * 8 + t + 4) * VS_STRIDE + n]);
                mma_m16n8k8(oacc[nj], aP, bb);
            }
        }
        __syncthreads();   // all warps done with Vs / Ks[cur] before next-iter writes
    }

    // ---- epilogue: normalize, write ctx combined-head ----
    float inv0 = 1.f / rs0, inv1 = 1.f / rs1;
    #pragma unroll
    for (int ni = 0; ni < 8; ni++) {
        int d = ni * 8 + 2 * t;
        size_t i0 = ((size_t)b * NS + qt * 128 + wm + g    ) * NDM + h * 64 + d;
        size_t i1 = ((size_t)b * NS + qt * 128 + wm + g + 8) * NDM + h * 64 + d;
        *(float2*)(g_ctx + i0) = make_float2(oacc[ni][0] * inv0, oacc[ni][1] * inv0);
        *(float2*)(g_ctx + i1) = make_float2(oacc[ni][2] * inv1, oacc[ni][3] * inv1);
    }
}

// ---------------------------------------------------------------------------
// Kernel 3: out = ctx @ Wo^T + bo (measured configuration).
// ---------------------------------------------------------------------------
__global__ __launch_bounds__(256) void out_proj_kernel(
    const float* __restrict__ Wo, const float* __restrict__ bo, float* __restrict__ out)
{
    extern __shared__ float smg[];
    float acc[4][4][4];
    #pragma unroll
    for (int i = 0; i < 4; i++)
        #pragma unroll
        for (int j = 0; j < 4; j++)
            #pragma unroll
            for (int k = 0; k < 4; k++) acc[i][j][k] = 0.f;

    gemm_tn_128x128_db(g_ctx + (size_t)blockIdx.y * 128 * NDM,
                       Wo    + (size_t)blockIdx.x * 128 * NDM, NDM, smg, acc);

    const int tid = threadIdx.x, lane = tid & 31, warp = tid >> 5;
    const int g = lane >> 2, t = lane & 3;
    const int wm0 = (warp & 1) * 64, wn0 = (warp >> 1) * 32;
    const int row0 = blockIdx.y * 128, col0 = blockIdx.x * 128;

    #pragma unroll
    for (int mi = 0; mi < 4; mi++) {
        #pragma unroll
        for (int ni = 0; ni < 4; ni++) {
            int n = col0 + wn0 + ni * 8 + 2 * t;
            float b0v = bo[n], b1v = bo[n + 1];
            #pragma unroll
            for (int half = 0; half < 2; half++) {
                int m = row0 + wm0 + mi * 16 + g + half * 8;
                *(float2*)(out + (size_t)m * NDM + n) =
                    make_float2(acc[mi][ni][half * 2 + 0] + b0v,
                                acc[mi][ni][half * 2 + 1] + b1v);
            }
        }
    }
}

// ---------------------------------------------------------------------------
// Launch
// ---------------------------------------------------------------------------
extern "C" void kernel_launch(void* const* d_in, const int* in_sizes, int n_in,
                              void* d_out, int out_size)
{
    (void)in_sizes; (void)n_in; (void)out_size;
    const float* Q      = (const float*)d_in[0];
    const float* K      = (const float*)d_in[1];
    const float* V      = (const float*)d_in[2];
    const float* Wq     = (const float*)d_in[3];
    const float* bq     = (const float*)d_in[4];
    const float* Wk     = (const float*)d_in[5];
    const float* bk     = (const float*)d_in[6];
    const float* Wv     = (const float*)d_in[7];
    const float* bv     = (const float*)d_in[8];
    const float* Wo     = (const float*)d_in[9];
    const float* bo     = (const float*)d_in[10];
    const float* relpos = (const float*)d_in[11];
    float* out = (float*)d_out;

    cudaFuncSetAttribute(flash_attn_kernel,
                         cudaFuncAttributeMaxDynamicSharedMemorySize, ATTN_SMEM_BYTES);
    cudaFuncSetAttribute(qkv_proj_kernel,
                         cudaFuncAttributeMaxDynamicSharedMemorySize, GEMM_SMEM_BYTES);
    cudaFuncSetAttribute(out_proj_kernel,
                         cudaFuncAttributeMaxDynamicSharedMemorySize, GEMM_SMEM_BYTES);

    dim3 blk(256);
    // 1) q,k,v = proj(Q/K/V), head-split, TF32-prerounded
    qkv_proj_kernel<<<dim3(NDM / 128, NT / 128, 3), blk, GEMM_SMEM_BYTES>>>(
        Q, K, V, Wq, Wk, Wv, bq, bk, bv);
    // 2) fused attention (relpos-seeded accumulators), batch-major grid for L2 relpos reuse
    flash_attn_kernel<<<dim3(NB, NS / 128, NH), blk, ATTN_SMEM_BYTES>>>(relpos);
    // 3) out = ctx @ Wo^T + bo
    out_proj_kernel<<<dim3(NDM / 128, NT / 128, 1), blk, GEMM_SMEM_BYTES>>>(Wo, bo, out);
}

// round 17
// speedup vs baseline: 1.0719x; 1.0171x over previous
#include <cuda_runtime.h>
#include <cstdint>
#include <cstddef>

// Problem constants
#define NB 4
#define NS 2048
#define NH 16
#define NDK 64
#define NDM 1024
#define NT (NB * NS)          // 8192 tokens
#define ATTN_SCALE 0.125f     // 1/sqrt(64) = 2^-3 (exact power of two)

// ---------------------------------------------------------------------------
// Scratch (device globals: no cudaMalloc allowed)
// g_q/g_k/g_v hold TF32-PREROUNDED values (cvt.rna at qkv epilogue;
// idempotent -> flash consuming them raw is bit-identical).
// ---------------------------------------------------------------------------
__device__ float g_q[(size_t)NB * NH * NS * NDK];        // 33.5 MB  [b][h][s][d]
__device__ float g_k[(size_t)NB * NH * NS * NDK];        // 33.5 MB
__device__ float g_v[(size_t)NB * NH * NS * NDK];        // 33.5 MB
__device__ float g_ctx[(size_t)NT * NDM];                // 33.5 MB  [b][s][h*64+d]

// ---------------------------------------------------------------------------
// Helpers
// ---------------------------------------------------------------------------
__device__ __forceinline__ unsigned f2tf_u(float f) {
    unsigned u;
    asm("cvt.rna.tf32.f32 %0, %1;" : "=r"(u) : "f"(f));
    return u;
}

__device__ __forceinline__ float f2tf(float f) {
    return __uint_as_float(f2tf_u(f));
}

__device__ __forceinline__ void mma_m16n8k8(float* c, const unsigned* a, const unsigned* b) {
    asm volatile(
        "mma.sync.aligned.m16n8k8.row.col.f32.tf32.tf32.f32 "
        "{%0,%1,%2,%3},{%4,%5,%6,%7},{%8,%9},{%0,%1,%2,%3};\n"
        : "+f"(c[0]), "+f"(c[1]), "+f"(c[2]), "+f"(c[3])
        : "r"(a[0]), "r"(a[1]), "r"(a[2]), "r"(a[3]), "r"(b[0]), "r"(b[1]));
}

__device__ __forceinline__ void cp_a16(float* smem_dst, const float* gsrc) {
    unsigned s = (unsigned)__cvta_generic_to_shared(smem_dst);
    asm volatile("cp.async.cg.shared.global [%0], [%1], 16;\n" :: "r"(s), "l"(gsrc));
}

// ---------------------------------------------------------------------------
// Double-buffered GEMM body (measured config: 351us, tensor=49%).
// ---------------------------------------------------------------------------
#define GEMM_SMEM_FLOATS (2 * 128 * 36 * 2)
#define GEMM_SMEM_BYTES  (GEMM_SMEM_FLOATS * 4)

__device__ __forceinline__ void gemm_tn_128x128_db(
    const float* __restrict__ A, const float* __restrict__ Bw, int Kd,
    float* sm, float acc[4][4][4])
{
    float* As = sm;                      // [2][128][36]
    float* Bs = sm + 2 * 128 * 36;       // [2][128][36]
    const int tid  = threadIdx.x;
    const int lane = tid & 31, warp = tid >> 5;
    const int g = lane >> 2, t = lane & 3;
    const int wm0 = (warp & 1) * 64, wn0 = (warp >> 1) * 32;

    const int nIter = Kd / 32;

    #pragma unroll
    for (int i = 0; i < 4; i++) {
        int s = tid + i * 256;
        int r = s >> 3, c4 = (s & 7) << 2;
        cp_a16(&As[(size_t)r * 36 + c4], A  + (size_t)r * Kd + c4);
        cp_a16(&Bs[(size_t)r * 36 + c4], Bw + (size_t)r * Kd + c4);
    }
    asm volatile("cp.async.commit_group;\n");

    for (int it = 0; it < nIter; it++) {
        const int cur = it & 1;
        if (it + 1 < nIter) {
            const int nxt = cur ^ 1;
            const int k0  = (it + 1) * 32;
            #pragma unroll
            for (int i = 0; i < 4; i++) {
                int s = tid + i * 256;
                int r = s >> 3, c4 = (s & 7) << 2;
                cp_a16(&As[((size_t)nxt * 128 + r) * 36 + c4], A  + (size_t)r * Kd + k0 + c4);
                cp_a16(&Bs[((size_t)nxt * 128 + r) * 36 + c4], Bw + (size_t)r * Kd + k0 + c4);
            }
            asm volatile("cp.async.commit_group;\n");
            asm volatile("cp.async.wait_group 1;\n");
        } else {
            asm volatile("cp.async.wait_group 0;\n");
        }
        __syncthreads();

        const float* Asb = As + (size_t)cur * 128 * 36;
        const float* Bsb = Bs + (size_t)cur * 128 * 36;

        #pragma unroll
        for (int ks = 0; ks < 32; ks += 8) {
            unsigned a[4][4], b[4][2];
            #pragma unroll
            for (int mi = 0; mi < 4; mi++) {
                int m = wm0 + mi * 16 + g;
                a[mi][0] = f2tf_u(Asb[(size_t)(m    ) * 36 + ks + t    ]);
                a[mi][1] = f2tf_u(Asb[(size_t)(m + 8) * 36 + ks + t    ]);
                a[mi][2] = f2tf_u(Asb[(size_t)(m    ) * 36 + ks + t + 4]);
                a[mi][3] = f2tf_u(Asb[(size_t)(m + 8) * 36 + ks + t + 4]);
            }
            #pragma unroll
            for (int ni = 0; ni < 4; ni++) {
                int n = wn0 + ni * 8 + g;
                b[ni][0] = f2tf_u(Bsb[(size_t)n * 36 + ks + t    ]);
                b[ni][1] = f2tf_u(Bsb[(size_t)n * 36 + ks + t + 4]);
            }
            #pragma unroll
            for (int mi = 0; mi < 4; mi++)
                #pragma unroll
                for (int ni = 0; ni < 4; ni++)
                    mma_m16n8k8(acc[mi][ni], a[mi], b[ni]);
        }
        __syncthreads();
    }
}

// ---------------------------------------------------------------------------
// Kernel 1: fused QKV projection, TF32-prerounded epilogue (measured 351us).
// ---------------------------------------------------------------------------
__global__ __launch_bounds__(256) void qkv_proj_kernel(
    const float* __restrict__ Qin, const float* __restrict__ Kin, const float* __restrict__ Vin,
    const float* __restrict__ Wq,  const float* __restrict__ Wk,  const float* __restrict__ Wv,
    const float* __restrict__ bq,  const float* __restrict__ bk,  const float* __restrict__ bv)
{
    extern __shared__ float smg[];
    const int z = blockIdx.z;
    const float* X    = (z == 0) ? Qin : (z == 1) ? Kin : Vin;
    const float* W    = (z == 0) ? Wq  : (z == 1) ? Wk  : Wv;
    const float* bias = (z == 0) ? bq  : (z == 1) ? bk  : bv;
    float* out        = (z == 0) ? g_q : (z == 1) ? g_k : g_v;

    float acc[4][4][4];
    #pragma unroll
    for (int i = 0; i < 4; i++)
        #pragma unroll
        for (int j = 0; j < 4; j++)
            #pragma unroll
            for (int k = 0; k < 4; k++) acc[i][j][k] = 0.f;

    gemm_tn_128x128_db(X + (size_t)blockIdx.y * 128 * NDM,
                       W + (size_t)blockIdx.x * 128 * NDM, NDM, smg, acc);

    const int tid = threadIdx.x, lane = tid & 31, warp = tid >> 5;
    const int g = lane >> 2, t = lane & 3;
    const int wm0 = (warp & 1) * 64, wn0 = (warp >> 1) * 32;
    const int row0 = blockIdx.y * 128, col0 = blockIdx.x * 128;

    #pragma unroll
    for (int mi = 0; mi < 4; mi++) {
        #pragma unroll
        for (int ni = 0; ni < 4; ni++) {
            int n = col0 + wn0 + ni * 8 + 2 * t;
            int h = n >> 6, d = n & 63;
            float b0v = bias[n], b1v = bias[n + 1];
            #pragma unroll
            for (int half = 0; half < 2; half++) {
                int m  = row0 + wm0 + mi * 16 + g + half * 8;
                int bb = m >> 11, s = m & 2047;
                size_t idx = (((size_t)(bb * NH + h) * NS) + s) * NDK + d;
                *(float2*)(out + idx) = make_float2(f2tf(acc[mi][ni][half * 2 + 0] + b0v),
                                                    f2tf(acc[mi][ni][half * 2 + 1] + b1v));
            }
        }
    }
}

// ---------------------------------------------------------------------------
// Kernel 2: flash attention — ONE barrier per iteration.
//   - relpos-seeded accumulators ((QK^T + rp*8)*2^-3, exact) as in round 16.
//   - K(kt+1) drained by the SAME wait_group 0 that drains V(kt); the single
//     post-wait __syncthreads publishes both -> the old pre-S barrier is gone.
//   - Vs double-buffered -> the old end-of-iteration barrier is gone; a fast
//     warp's seed/prefetch/S of kt+1 overlaps slow warps' P@V(kt).
//   Per-iter: seed -> issue GV(kt),GK(kt) -> S-MMA(Ks[cur]) -> softmax ->
//             wait_group 0 -> __syncthreads -> P@V(Vs[cur]).
//   kt==0 only: extra wait+barrier for the {Q,K(0)} prologue group.
// SMEM: Qs[128][68] + Ks[2][128][68] + Vs[2][128][72] = 174 KB -> 1 CTA/SM.
// ---------------------------------------------------------------------------
#define QS_STRIDE 68
#define KS_STRIDE 68
#define VS_STRIDE 72
#define ATTN_SMEM_FLOATS (128 * (QS_STRIDE + 2 * KS_STRIDE + 2 * VS_STRIDE))
#define ATTN_SMEM_BYTES  (ATTN_SMEM_FLOATS * 4)

__global__ __launch_bounds__(256, 1) void flash_attn_kernel(const float* __restrict__ relpos)
{
    extern __shared__ float sm[];
    float* Qs = sm;                                   // [128][68]
    float* Ks = Qs + 128 * QS_STRIDE;                 // [2][128][68] (rows sigma-permuted)
    float* Vs = Ks + 2 * 128 * KS_STRIDE;             // [2][128][72] (rows natural)

    const int b = blockIdx.x, qt = blockIdx.y, h = blockIdx.z;
    const int bh = b * NH + h;
    const float* qp = g_q + (size_t)bh * NS * NDK + (size_t)qt * 128 * NDK;
    const float* kp = g_k + (size_t)bh * NS * NDK;
    const float* vp = g_v + (size_t)bh * NS * NDK;
    const float* rp = relpos + (size_t)h * NS * NS + (size_t)qt * 128 * NS;

    const int tid = threadIdx.x, lane = tid & 31, warp = tid >> 5;
    const int g = lane >> 2, t = lane & 3;
    const int wm = warp * 16;

    // prologue: Q (natural) + K(0) (sigma rows) in one cp.async group G0.
    #pragma unroll
    for (int i = 0; i < 8; i++) {
        int s = tid + i * 256;
        int r = s >> 4, c4 = (s & 15) << 2;
        cp_a16(&Qs[(size_t)r * QS_STRIDE + c4], qp + (size_t)r * NDK + c4);
        int c = r & 7;
        int srow = (r & ~7) | ((c >> 1) + ((c & 1) << 2));   // sigma
        cp_a16(&Ks[(size_t)r * KS_STRIDE + c4], kp + (size_t)srow * NDK + c4);
    }
    asm volatile("cp.async.commit_group;\n");

    float rm0 = -INFINITY, rm1 = -INFINITY;   // running max, rows (wm+g), (wm+g+8)
    float rs0 = 0.f, rs1 = 0.f;               // running sum
    float oacc[8][4];
    #pragma unroll
    for (int i = 0; i < 8; i++)
        #pragma unroll
        for (int j = 0; j < 4; j++) oacc[i][j] = 0.f;

    unsigned qreg[8][4];                      // Q fragments, loaded at kt==0

    for (int kt = 0; kt < NS / 128; kt++) {
        const int cur = kt & 1;

        // ---- 1. seed S accumulators with relpos*8 (exact; LDG latency
        //         overlaps other warps' P@V of the previous iteration) ----
        float sacc[16][4];
        {
            const float* rp0 = rp + (size_t)(wm + g    ) * NS + kt * 128 + t;
            const float* rp1 = rp + (size_t)(wm + g + 8) * NS + kt * 128 + t;
            #pragma unroll
            for (int ni = 0; ni < 16; ni++) {
                sacc[ni][0] = rp0[ni * 8    ] * 8.f;
                sacc[ni][1] = rp0[ni * 8 + 4] * 8.f;
                sacc[ni][2] = rp1[ni * 8    ] * 8.f;
                sacc[ni][3] = rp1[ni * 8 + 4] * 8.f;
            }
        }

        // ---- 2. issue GV(kt): V(kt) -> Vs[cur]; GK(kt): K(kt+1) -> Ks[nxt] ----
        {
            const float* vsrc = vp + (size_t)kt * 128 * NDK;
            float* vdst = Vs + (size_t)cur * 128 * VS_STRIDE;
            #pragma unroll
            for (int i = 0; i < 8; i++) {
                int s = tid + i * 256;
                int r = s >> 4, c4 = (s & 15) << 2;
                cp_a16(&vdst[(size_t)r * VS_STRIDE + c4], vsrc + (size_t)r * NDK + c4);
            }
            asm volatile("cp.async.commit_group;\n");
        }
        if (kt + 1 < NS / 128) {
            const float* ksrc = kp + (size_t)(kt + 1) * 128 * NDK;
            float* kdst = Ks + (size_t)(cur ^ 1) * 128 * KS_STRIDE;
            #pragma unroll
            for (int i = 0; i < 8; i++) {
                int s = tid + i * 256;
                int r = s >> 4, c4 = (s & 15) << 2;
                int c = r & 7;
                int srow = (r & ~7) | ((c >> 1) + ((c & 1) << 2));
                cp_a16(&kdst[(size_t)r * KS_STRIDE + c4], ksrc + (size_t)srow * NDK + c4);
            }
            asm volatile("cp.async.commit_group;\n");
        }

        // ---- 2b. first iteration: drain prologue {Q,K(0)}, publish ----
        if (kt == 0) {
            asm volatile("cp.async.wait_group 2;\n");   // drains G0 only
            __syncthreads();
            #pragma unroll
            for (int ks = 0; ks < 8; ks++) {
                qreg[ks][0] = __float_as_uint(Qs[(size_t)(wm + g    ) * QS_STRIDE + ks * 8 + t    ]);
                qreg[ks][1] = __float_as_uint(Qs[(size_t)(wm + g + 8) * QS_STRIDE + ks * 8 + t    ]);
                qreg[ks][2] = __float_as_uint(Qs[(size_t)(wm + g    ) * QS_STRIDE + ks * 8 + t + 4]);
                qreg[ks][3] = __float_as_uint(Qs[(size_t)(wm + g + 8) * QS_STRIDE + ks * 8 + t + 4]);
            }
        }

        const float* Ksb = Ks + (size_t)cur * 128 * KS_STRIDE;

        // ---- 3. S = rp*8 + Q K^T : warp tile m16 x n128(slots), k=64 ----
        #pragma unroll
        for (int ks = 0; ks < 8; ks++) {
            #pragma unroll
            for (int ni = 0; ni < 16; ni++) {
                unsigned bb[2];
                int n = ni * 8 + g;
                bb[0] = __float_as_uint(Ksb[(size_t)n * KS_STRIDE + ks * 8 + t    ]);
                bb[1] = __float_as_uint(Ksb[(size_t)n * KS_STRIDE + ks * 8 + t + 4]);
                mma_m16n8k8(sacc[ni], qreg[ks], bb);
            }
        }

        // ---- 4. scale by 2^-3 (exact), softmax ----
        float m0 = -INFINITY, m1 = -INFINITY;
        #pragma unroll
        for (int ni = 0; ni < 16; ni++) {
            sacc[ni][0] *= ATTN_SCALE;
            sacc[ni][1] *= ATTN_SCALE;
            sacc[ni][2] *= ATTN_SCALE;
            sacc[ni][3] *= ATTN_SCALE;
            m0 = fmaxf(m0, fmaxf(sacc[ni][0], sacc[ni][1]));
            m1 = fmaxf(m1, fmaxf(sacc[ni][2], sacc[ni][3]));
        }
        m0 = fmaxf(m0, __shfl_xor_sync(0xFFFFFFFFu, m0, 1));
        m0 = fmaxf(m0, __shfl_xor_sync(0xFFFFFFFFu, m0, 2));
        m1 = fmaxf(m1, __shfl_xor_sync(0xFFFFFFFFu, m1, 1));
        m1 = fmaxf(m1, __shfl_xor_sync(0xFFFFFFFFu, m1, 2));

        float nm0 = fmaxf(rm0, m0), nm1 = fmaxf(rm1, m1);
        float al0 = __expf(rm0 - nm0), al1 = __expf(rm1 - nm1);
        rm0 = nm0; rm1 = nm1;

        float ps0 = 0.f, ps1 = 0.f;
        #pragma unroll
        for (int ni = 0; ni < 16; ni++) {
            sacc[ni][0] = __expf(sacc[ni][0] - nm0);
            sacc[ni][1] = __expf(sacc[ni][1] - nm0);
            sacc[ni][2] = __expf(sacc[ni][2] - nm1);
            sacc[ni][3] = __expf(sacc[ni][3] - nm1);
            ps0 += sacc[ni][0] + sacc[ni][1];
            ps1 += sacc[ni][2] + sacc[ni][3];
        }
        ps0 += __shfl_xor_sync(0xFFFFFFFFu, ps0, 1);
        ps0 += __shfl_xor_sync(0xFFFFFFFFu, ps0, 2);
        ps1 += __shfl_xor_sync(0xFFFFFFFFu, ps1, 1);
        ps1 += __shfl_xor_sync(0xFFFFFFFFu, ps1, 2);
        rs0 = rs0 * al0 + ps0;
        rs1 = rs1 * al1 + ps1;

        #pragma unroll
        for (int ni = 0; ni < 8; ni++) {
            oacc[ni][0] *= al0; oacc[ni][1] *= al0;
            oacc[ni][2] *= al1; oacc[ni][3] *= al1;
        }

        // ---- 5+6. drain V(kt) AND K(kt+1); single publish barrier ----
        asm volatile("cp.async.wait_group 0;\n");
        __syncthreads();

        // ---- 7. O += P V on Vs[cur] (P A-fragments straight from sacc) ----
        const float* Vsb = Vs + (size_t)cur * 128 * VS_STRIDE;
        #pragma unroll
        for (int ni = 0; ni < 16; ni++) {          // key-block = k-block
            unsigned aP[4];
            aP[0] = f2tf_u(sacc[ni][0]);   // (row g,   k=t)
            aP[1] = f2tf_u(sacc[ni][2]);   // (row g+8, k=t)
            aP[2] = f2tf_u(sacc[ni][1]);   // (row g,   k=t+4)
            aP[3] = f2tf_u(sacc[ni][3]);   // (row g+8, k=t+4)
            #pragma unroll
            for (int nj = 0; nj < 8; nj++) {
                unsigned bb[2];
                int n = nj * 8 + g;
                bb[0] = __float_as_uint(Vsb[(size_t)(ni * 8 + t    ) * VS_STRIDE + n]);
                bb[1] = __float_as_uint(Vsb[(size_t)(ni * 8 + t + 4) * VS_STRIDE + n]);
                mma_m16n8k8(oacc[nj], aP, bb);
            }
        }
        // no end-of-iteration barrier: Vs is double-buffered, and the next
        // iteration's Ks[nxt] writes are ordered by this iteration's barrier.
    }

    // ---- epilogue: normalize, write ctx combined-head ----
    float inv0 = 1.f / rs0, inv1 = 1.f / rs1;
    #pragma unroll
    for (int ni = 0; ni < 8; ni++) {
        int d = ni * 8 + 2 * t;
        size_t i0 = ((size_t)b * NS + qt * 128 + wm + g    ) * NDM + h * 64 + d;
        size_t i1 = ((size_t)b * NS + qt * 128 + wm + g + 8) * NDM + h * 64 + d;
        *(float2*)(g_ctx + i0) = make_float2(oacc[ni][0] * inv0, oacc[ni][1] * inv0);
        *(float2*)(g_ctx + i1) = make_float2(oacc[ni][2] * inv1, oacc[ni][3] * inv1);
    }
}

// ---------------------------------------------------------------------------
// Kernel 3: out = ctx @ Wo^T + bo (measured configuration).
// ---------------------------------------------------------------------------
__global__ __launch_bounds__(256) void out_proj_kernel(
    const float* __restrict__ Wo, const float* __restrict__ bo, float* __restrict__ out)
{
    extern __shared__ float smg[];
    float acc[4][4][4];
    #pragma unroll
    for (int i = 0; i < 4; i++)
        #pragma unroll
        for (int j = 0; j < 4; j++)
            #pragma unroll
            for (int k = 0; k < 4; k++) acc[i][j][k] = 0.f;

    gemm_tn_128x128_db(g_ctx + (size_t)blockIdx.y * 128 * NDM,
                       Wo    + (size_t)blockIdx.x * 128 * NDM, NDM, smg, acc);

    const int tid = threadIdx.x, lane = tid & 31, warp = tid >> 5;
    const int g = lane >> 2, t = lane & 3;
    const int wm0 = (warp & 1) * 64, wn0 = (warp >> 1) * 32;
    const int row0 = blockIdx.y * 128, col0 = blockIdx.x * 128;

    #pragma unroll
    for (int mi = 0; mi < 4; mi++) {
        #pragma unroll
        for (int ni = 0; ni < 4; ni++) {
            int n = col0 + wn0 + ni * 8 + 2 * t;
            float b0v = bo[n], b1v = bo[n + 1];
            #pragma unroll
            for (int half = 0; half < 2; half++) {
                int m = row0 + wm0 + mi * 16 + g + half * 8;
                *(float2*)(out + (size_t)m * NDM + n) =
                    make_float2(acc[mi][ni][half * 2 + 0] + b0v,
                                acc[mi][ni][half * 2 + 1] + b1v);
            }
        }
    }
}

// ---------------------------------------------------------------------------
// Launch
// ---------------------------------------------------------------------------
extern "C" void kernel_launch(void* const* d_in, const int* in_sizes, int n_in,
                              void* d_out, int out_size)
{
    (void)in_sizes; (void)n_in; (void)out_size;
    const float* Q      = (const float*)d_in[0];
    const float* K      = (const float*)d_in[1];
    const float* V      = (const float*)d_in[2];
    const float* Wq     = (const float*)d_in[3];
    const float* bq     = (const float*)d_in[4];
    const float* Wk     = (const float*)d_in[5];
    const float* bk     = (const float*)d_in[6];
    const float* Wv     = (const float*)d_in[7];
    const float* bv     = (const float*)d_in[8];
    const float* Wo     = (const float*)d_in[9];
    const float* bo     = (const float*)d_in[10];
    const float* relpos = (const float*)d_in[11];
    float* out = (float*)d_out;

    cudaFuncSetAttribute(flash_attn_kernel,
                         cudaFuncAttributeMaxDynamicSharedMemorySize, ATTN_SMEM_BYTES);
    cudaFuncSetAttribute(qkv_proj_kernel,
                         cudaFuncAttributeMaxDynamicSharedMemorySize, GEMM_SMEM_BYTES);
    cudaFuncSetAttribute(out_proj_kernel,
                         cudaFuncAttributeMaxDynamicSharedMemorySize, GEMM_SMEM_BYTES);

    dim3 blk(256);
    // 1) q,k,v = proj(Q/K/V), head-split, TF32-prerounded
    qkv_proj_kernel<<<dim3(NDM / 128, NT / 128, 3), blk, GEMM_SMEM_BYTES>>>(
        Q, K, V, Wq, Wk, Wv, bq, bk, bv);
    // 2) fused attention (1 barrier/iter), batch-major grid for L2 relpos reuse
    flash_attn_kernel<<<dim3(NB, NS / 128, NH), blk, ATTN_SMEM_BYTES>>>(relpos);
    // 3) out = ctx @ Wo^T + bo
    out_proj_kernel<<<dim3(NDM / 128, NT / 128, 1), blk, GEMM_SMEM_BYTES>>>(Wo, bo, out);
}